// round 11
// baseline (speedup 1.0000x reference)
#include <cuda_runtime.h>
#include <math.h>
#include <stdint.h>

// Problem constants
#define NB      65536
#define FDIM    1024
#define DVQ     64
#define KCODES  512
#define RPC     64
#define NCTA    (NB / RPC)       // 1024
#define THREADS 128

typedef unsigned long long ull;

// Shared-memory layout (float offsets)
//  bufA  [64][132]  activation ping                         8448 fl
//  bufB  [64][132]  activation pong / GEMM1 staging area    8448 fl
//        (GEMM1: Xs[64][36]=2304 @bufB, Ws[32][192]=6144 @bufB+2304)
//  xqs   [64][68]   VQ projection                           4352 fl
//  stage 4424 fl:   chain Wdb[2][16][132]=4224 | VQ EsT[64][68]+Enorm[64]+wsum
#define BUFA_OFF   0
#define BUFB_OFF   (64 * 132)
#define XQ_OFF     (BUFB_OFF + 64 * 132)
#define STAGE_OFF  (XQ_OFF + 64 * 68)
#define STAGE_FL   4424
#define SMEM_BYTES ((STAGE_OFF + STAGE_FL) * 4)   // 102688 B -> 2 CTAs/SM

__device__ float        g_part[NCTA];
__device__ unsigned int g_ctr = 0;

// ---- packed fp32x2 helpers (exact IEEE fp32 per lane, 2x FFMA throughput) ----
__device__ __forceinline__ ull pk2(float a, float b) {
    ull r; asm("mov.b64 %0,{%1,%2};" : "=l"(r) : "f"(a), "f"(b)); return r;
}
__device__ __forceinline__ void ffma2(ull& d, ull a, ull b) {
    asm("fma.rn.f32x2 %0,%1,%2,%3;" : "=l"(d) : "l"(a), "l"(b), "l"(d));
}
__device__ __forceinline__ float2 up2(ull v) {
    float2 f; asm("mov.b64 {%0,%1},%2;" : "=f"(f.x), "=f"(f.y) : "l"(v)); return f;
}

// ---------------------------------------------------------------------------
// 64x128 @ 128x128 chain GEMM. A read DIRECTLY from smem activations (no
// staging); W streamed from gmem through a double-buffered 16-row stage
// (one __syncthreads per chunk). Thread tile 8 rows x 8 cols. Cs may alias As.
// ---------------------------------------------------------------------------
__device__ __forceinline__ void gemm_chain(
    const float* __restrict__ Wg, const float* __restrict__ bias,
    const float* As, float* Cs, float* stage, int tid, bool relu)
{
    const int tx = tid & 15;     // cols tx*8 .. tx*8+7
    const int ty = tid >> 4;     // rows ty*8 .. ty*8+7
    float* Wdb = stage;          // [2][16*132]
    ull acc[8][4];
#pragma unroll
    for (int i = 0; i < 8; ++i)
#pragma unroll
        for (int j = 0; j < 4; ++j) acc[i][j] = 0ULL;

    // preload chunk 0
#pragma unroll
    for (int t = 0; t < 4; ++t) {
        int idx = tid + t * THREADS;          // 512 float4
        int kk = idx >> 5, q = idx & 31;
        float4 v = *((const float4*)(Wg + (size_t)kk * 128 + q * 4));
        *((float4*)(Wdb + kk * 132 + q * 4)) = v;
    }
    __syncthreads();

    for (int kc = 0; kc < 8; ++kc) {
        float* Wcur = Wdb + (kc & 1) * (16 * 132);
        if (kc < 7) {                         // stage next chunk into other buffer
            float* Wnxt = Wdb + ((kc + 1) & 1) * (16 * 132);
#pragma unroll
            for (int t = 0; t < 4; ++t) {
                int idx = tid + t * THREADS;
                int kk = idx >> 5, q = idx & 31;
                float4 v = *((const float4*)(Wg + (size_t)((kc + 1) * 16 + kk) * 128 + q * 4));
                *((float4*)(Wnxt + kk * 132 + q * 4)) = v;
            }
        }
        const float* Ab = As + ty * 8 * 132 + kc * 16;
#pragma unroll
        for (int kk4 = 0; kk4 < 4; ++kk4) {
            float4 a4[8];
#pragma unroll
            for (int i = 0; i < 8; ++i)
                a4[i] = *((const float4*)(Ab + i * 132 + kk4 * 4));
#pragma unroll
            for (int kkin = 0; kkin < 4; ++kkin) {
                ull pa[8];
#pragma unroll
                for (int i = 0; i < 8; ++i) {
                    const float* af = (const float*)&a4[i];
                    float a = af[kkin];
                    pa[i] = pk2(a, a);
                }
                const ulonglong2* bp =
                    (const ulonglong2*)(Wcur + (kk4 * 4 + kkin) * 132 + tx * 8);
                ulonglong2 b01 = bp[0], b23 = bp[1];
                ull b[4] = {b01.x, b01.y, b23.x, b23.y};
#pragma unroll
                for (int i = 0; i < 8; ++i)
#pragma unroll
                    for (int j = 0; j < 4; ++j) ffma2(acc[i][j], pa[i], b[j]);
            }
        }
        __syncthreads();   // chunk consumed by all; next-next stage may overwrite
    }
    float bb[8];
#pragma unroll
    for (int j = 0; j < 8; ++j) bb[j] = bias[tx * 8 + j];
#pragma unroll
    for (int i = 0; i < 8; ++i) {
        int r = ty * 8 + i;
#pragma unroll
        for (int j = 0; j < 4; ++j) {
            float2 v = up2(acc[i][j]);
            float v0 = v.x + bb[2 * j], v1 = v.y + bb[2 * j + 1];
            if (relu) { v0 = fmaxf(v0, 0.f); v1 = fmaxf(v1, 0.f); }
            Cs[r * 132 + tx * 8 + 2 * j]     = v0;
            Cs[r * 132 + tx * 8 + 2 * j + 1] = v1;
        }
    }
    __syncthreads();
}

// ---------------------------------------------------------------------------
// Single fused kernel: one CTA = 64 batch rows end-to-end; last CTA finishes
// the vq_loss reduction (one launch per call).
// ---------------------------------------------------------------------------
extern __shared__ float smem[];

__global__ void __launch_bounds__(THREADS, 2)
acsq_kernel(const float* __restrict__ x,
            const float* __restrict__ W_e0, const float* __restrict__ b_e0,
            const float* __restrict__ W_e1, const float* __restrict__ b_e1,
            const float* __restrict__ W_e2, const float* __restrict__ b_e2,
            const float* __restrict__ W_p,  const float* __restrict__ b_p,
            const float* __restrict__ E,
            const float* __restrict__ W_a0, const float* __restrict__ b_a0,
            const float* __restrict__ W_a1, const float* __restrict__ b_a1,
            const float* __restrict__ W_c0, const float* __restrict__ b_c0,
            const float* __restrict__ W_c1, const float* __restrict__ b_c1,
            const float* __restrict__ W_c2, const float* __restrict__ b_c2,
            float* __restrict__ out_probs, float* __restrict__ out_critic,
            float* __restrict__ out_vq,    float* __restrict__ out_idx)
{
    float* bufA  = smem + BUFA_OFF;
    float* bufB  = smem + BUFB_OFF;
    float* xqs   = smem + XQ_OFF;
    float* stage = smem + STAGE_OFF;
    const int tid  = threadIdx.x;
    const int row0 = blockIdx.x * RPC;

    // ============== GEMM1: X[64x1024] @ [W_e0 | W_p] [1024x192] ==============
    // Thread tile 8 rows x 12 cols. Staging lives in bufB (idle until chain).
    {
        const int tx = tid & 15;   // cols tx*12 .. tx*12+11  (0..191)
        const int ty = tid >> 4;   // rows ty*8 .. ty*8+7
        float* Xs = bufB;              // [64][36]
        float* Ws = bufB + 64 * 36;    // [32][192]
        ull acc[8][6];
#pragma unroll
        for (int i = 0; i < 8; ++i)
#pragma unroll
            for (int j = 0; j < 6; ++j) acc[i][j] = 0ULL;

        for (int kc = 0; kc < 32; ++kc) {
            // X chunk [64 rows][32 k] : 512 float4, 4 per thread
#pragma unroll
            for (int t = 0; t < 4; ++t) {
                int idx = tid + t * THREADS;
                int r = idx >> 3, q = idx & 7;
                float4 v = *((const float4*)(x + (size_t)(row0 + r) * FDIM + kc * 32 + q * 4));
                *((float4*)(Xs + r * 36 + q * 4)) = v;
            }
            // W chunk [32 k][192]: 128 cols W_e0 + 64 cols W_p : 1536 float4
#pragma unroll
            for (int t = 0; t < 12; ++t) {
                int idx = tid + t * THREADS;
                int kk = idx / 48, q = idx % 48;
                int krow = kc * 32 + kk;
                float4 v;
                if (q < 32) v = *((const float4*)(W_e0 + (size_t)krow * 128 + q * 4));
                else        v = *((const float4*)(W_p  + (size_t)krow * 64 + (q - 32) * 4));
                *((float4*)(Ws + kk * 192 + q * 4)) = v;
            }
            __syncthreads();
            const float* Xb = Xs + ty * 8 * 36;
#pragma unroll
            for (int kk4 = 0; kk4 < 8; ++kk4) {
                float4 a4[8];
#pragma unroll
                for (int i = 0; i < 8; ++i)
                    a4[i] = *((const float4*)(Xb + i * 36 + kk4 * 4));
#pragma unroll
                for (int kkin = 0; kkin < 4; ++kkin) {
                    ull pa[8];
#pragma unroll
                    for (int i = 0; i < 8; ++i) {
                        const float* af = (const float*)&a4[i];
                        float a = af[kkin];
                        pa[i] = pk2(a, a);
                    }
                    const ulonglong2* bp =
                        (const ulonglong2*)(Ws + (kk4 * 4 + kkin) * 192 + tx * 12);
                    ulonglong2 b01 = bp[0], b23 = bp[1], b45 = bp[2];
                    ull b[6] = {b01.x, b01.y, b23.x, b23.y, b45.x, b45.y};
#pragma unroll
                    for (int i = 0; i < 8; ++i)
#pragma unroll
                        for (int j = 0; j < 6; ++j) ffma2(acc[i][j], pa[i], b[j]);
                }
            }
            __syncthreads();
        }
        // Epilogue: cols [0,128) -> emb0 = relu(+b_e0); cols [128,192) -> xq (+b_p)
#pragma unroll
        for (int i = 0; i < 8; ++i) {
            int r = ty * 8 + i;
#pragma unroll
            for (int j = 0; j < 6; ++j) {
                float2 v = up2(acc[i][j]);
                int c0 = tx * 12 + 2 * j;
                if (c0 < 128) bufA[r * 132 + c0] = fmaxf(v.x + b_e0[c0], 0.f);
                else          xqs[r * 68 + (c0 - 128)] = v.x + b_p[c0 - 128];
                int c1 = c0 + 1;
                if (c1 < 128) bufA[r * 132 + c1] = fmaxf(v.y + b_e0[c1], 0.f);
                else          xqs[r * 68 + (c1 - 128)] = v.y + b_p[c1 - 128];
            }
        }
        __syncthreads();
    }

    // ============== VQ: argmin_k (||E_k||^2 - 2 xq.E_k), e_latent partials ===
    {
        float* EsT   = stage;                // [64 d][68] transposed codes
        float* Enorm = stage + 64 * 68;      // [64]
        float* wsum  = stage + 64 * 68 + 64; // [4]
        const int cg = tid & 7;              // code subgroup: codes cg*8..cg*8+7
        const int rg = tid >> 3;             // 0..15
        const int r0 = rg * 4;               // 4 rows per thread
        float best[4]; int bidx[4];
#pragma unroll
        for (int i = 0; i < 4; ++i) { best[i] = 3.402823e38f; bidx[i] = 0; }

        for (int cc = 0; cc < 8; ++cc) {
            // stage 64 codes transposed: EsT[d][c] = E[cc*64+c][d]
#pragma unroll
            for (int t = 0; t < 8; ++t) {
                int idx = tid + t * THREADS;
                int dq = idx >> 6, c = idx & 63;
                float4 v = *((const float4*)(E + (size_t)(cc * 64 + c) * DVQ + dq * 4));
                EsT[(dq * 4 + 0) * 68 + c] = v.x;
                EsT[(dq * 4 + 1) * 68 + c] = v.y;
                EsT[(dq * 4 + 2) * 68 + c] = v.z;
                EsT[(dq * 4 + 3) * 68 + c] = v.w;
            }
            __syncthreads();
            if (tid < 64) {
                float s = 0.f;
#pragma unroll 8
                for (int d = 0; d < DVQ; ++d) { float e = EsT[d * 68 + tid]; s = fmaf(e, e, s); }
                Enorm[tid] = s;
            }
            __syncthreads();

            ull acc[4][4];
#pragma unroll
            for (int i = 0; i < 4; ++i)
#pragma unroll
                for (int j = 0; j < 4; ++j) acc[i][j] = 0ULL;

#pragma unroll
            for (int d4 = 0; d4 < 16; ++d4) {
                float4 a4[4];
#pragma unroll
                for (int i = 0; i < 4; ++i)
                    a4[i] = *((const float4*)(xqs + (r0 + i) * 68 + d4 * 4));
#pragma unroll
                for (int din = 0; din < 4; ++din) {
                    ull pa[4];
#pragma unroll
                    for (int i = 0; i < 4; ++i) {
                        const float* af = (const float*)&a4[i];
                        float a = af[din];
                        pa[i] = pk2(a, a);
                    }
                    const ulonglong2* bp =
                        (const ulonglong2*)(EsT + (d4 * 4 + din) * 68 + cg * 8);
                    ulonglong2 b01 = bp[0], b23 = bp[1];
                    ull b[4] = {b01.x, b01.y, b23.x, b23.y};
#pragma unroll
                    for (int i = 0; i < 4; ++i)
#pragma unroll
                        for (int j = 0; j < 4; ++j) ffma2(acc[i][j], pa[i], b[j]);
                }
            }
#pragma unroll
            for (int j = 0; j < 4; ++j) {
                int c0 = cg * 8 + 2 * j;
                float n0 = Enorm[c0], n1 = Enorm[c0 + 1];
                int g0 = cc * 64 + c0;
#pragma unroll
                for (int i = 0; i < 4; ++i) {
                    float2 dv = up2(acc[i][j]);
                    float s;
                    s = fmaf(-2.f, dv.x, n0); if (s < best[i]) { best[i] = s; bidx[i] = g0; }
                    s = fmaf(-2.f, dv.y, n1); if (s < best[i]) { best[i] = s; bidx[i] = g0 + 1; }
                }
            }
            __syncthreads();
        }
        // reduce over the 8 code subgroups (lanes xor 1,2,4), first-index tie-break
#pragma unroll
        for (int i = 0; i < 4; ++i) {
            float v = best[i]; int bi = bidx[i];
#pragma unroll
            for (int o = 1; o <= 4; o <<= 1) {
                float ov = __shfl_xor_sync(0xffffffffu, v, o);
                int   oi = __shfl_xor_sync(0xffffffffu, bi, o);
                if (ov < v || (ov == v && oi < bi)) { v = ov; bi = oi; }
            }
            best[i] = v; bidx[i] = bi;
        }
        // e_latent partial (deterministic warp/CTA reduction)
        float s_lat = 0.f;
        if (cg == 0) {
#pragma unroll
            for (int i = 0; i < 4; ++i) {
                int r = r0 + i;
                out_idx[row0 + r] = (float)bidx[i];
                const float* e = E + (size_t)bidx[i] * DVQ;
                float s = 0.f;
#pragma unroll 8
                for (int d = 0; d < DVQ; ++d) {
                    float diff = e[d] - xqs[r * 68 + d];
                    s = fmaf(diff, diff, s);
                }
                s_lat += s;
            }
        }
#pragma unroll
        for (int o = 16; o >= 1; o >>= 1)
            s_lat += __shfl_xor_sync(0xffffffffu, s_lat, o);
        if ((tid & 31) == 0) wsum[tid >> 5] = s_lat;
        __syncthreads();
        if (tid == 0) {
            float t = 0.f;
#pragma unroll
            for (int w = 0; w < 4; ++w) t += wsum[w];
            g_part[blockIdx.x] = t;
        }
        __syncthreads();   // stage reused by chain GEMMs below
    }

    // ============== MLP chain (activations resident in smem) =================
    // bufA = emb0
    gemm_chain(W_e1, b_e1, bufA, bufB, stage, tid, true);   // emb1   -> bufB
    gemm_chain(W_e2, b_e2, bufB, bufA, stage, tid, true);   // emb2   -> bufA
    gemm_chain(W_a0, b_a0, bufA, bufB, stage, tid, true);   // a_act  -> bufB
    gemm_chain(W_c0, b_c0, bufA, bufA, stage, tid, true);   // c0     -> bufA (in place)
    gemm_chain(W_a1, b_a1, bufB, bufB, stage, tid, false);  // logits -> bufB (in place)
    gemm_chain(W_c1, b_c1, bufA, bufA, stage, tid, true);   // c1     -> bufA (in place)

    // ============== critic weight stage + softmax ============================
    stage[tid] = W_c2[tid];   // 128 threads = 128 weights

    {   // softmax over bufB rows -> out_probs
        int warp = tid >> 5, lane = tid & 31;
        for (int r = warp; r < RPC; r += 4) {
            float4 v = *((float4*)(bufB + r * 132 + lane * 4));
            float m = fmaxf(fmaxf(v.x, v.y), fmaxf(v.z, v.w));
#pragma unroll
            for (int o = 16; o >= 1; o >>= 1)
                m = fmaxf(m, __shfl_xor_sync(0xffffffffu, m, o));
            float e0 = expf(v.x - m), e1 = expf(v.y - m);
            float e2 = expf(v.z - m), e3 = expf(v.w - m);
            float s = (e0 + e1) + (e2 + e3);
#pragma unroll
            for (int o = 16; o >= 1; o >>= 1)
                s += __shfl_xor_sync(0xffffffffu, s, o);
            float4 p = make_float4(e0 / s, e1 / s, e2 / s, e3 / s);
            *((float4*)(out_probs + (size_t)(row0 + r) * 128 + lane * 4)) = p;
        }
    }
    __syncthreads();

    // ============== critic head: c1 @ W_c2 + b_c2 ============================
    if (tid < RPC) {
        float dotv = 0.f;
#pragma unroll 8
        for (int d = 0; d < 128; ++d)
            dotv = fmaf(bufA[tid * 132 + d], stage[d], dotv);
        out_critic[row0 + tid] = dotv + b_c2[0];
    }
    __syncthreads();

    // ============== last-CTA vq_loss finalize (single-launch design) =========
    __threadfence();
    unsigned int* flag = (unsigned int*)stage;
    if (tid == 0) {
        unsigned int p = atomicAdd(&g_ctr, 1u);
        flag[0] = (p == NCTA - 1) ? 1u : 0u;
    }
    __syncthreads();
    if (flag[0]) {
        float s = 0.f;
        for (int i = tid; i < NCTA; i += THREADS) s += g_part[i];
#pragma unroll
        for (int o = 16; o >= 1; o >>= 1)
            s += __shfl_xor_sync(0xffffffffu, s, o);
        if ((tid & 31) == 0) stage[8 + (tid >> 5)] = s;
        __syncthreads();
        if (tid == 0) {
            float t = 0.f;
#pragma unroll
            for (int w = 0; w < 4; ++w) t += stage[8 + w];
            out_vq[0] = (float)((double)t * (1.25 / ((double)NB * (double)DVQ)));
            g_ctr = 0;   // reset for next graph replay
        }
    }
}

// ---------------------------------------------------------------------------
extern "C" void kernel_launch(void* const* d_in, const int* in_sizes, int n_in,
                              void* d_out, int out_size)
{
    const float* x    = (const float*)d_in[0];
    const float* W_e0 = (const float*)d_in[1];
    const float* b_e0 = (const float*)d_in[2];
    const float* W_e1 = (const float*)d_in[3];
    const float* b_e1 = (const float*)d_in[4];
    const float* W_e2 = (const float*)d_in[5];
    const float* b_e2 = (const float*)d_in[6];
    const float* W_p  = (const float*)d_in[7];
    const float* b_p  = (const float*)d_in[8];
    const float* E    = (const float*)d_in[9];
    const float* W_a0 = (const float*)d_in[10];
    const float* b_a0 = (const float*)d_in[11];
    const float* W_a1 = (const float*)d_in[12];
    const float* b_a1 = (const float*)d_in[13];
    const float* W_c0 = (const float*)d_in[14];
    const float* b_c0 = (const float*)d_in[15];
    const float* W_c1 = (const float*)d_in[16];
    const float* b_c1 = (const float*)d_in[17];
    const float* W_c2 = (const float*)d_in[18];
    const float* b_c2 = (const float*)d_in[19];

    float* o = (float*)d_out;
    const size_t P = (size_t)NB * 128;
    float* out_probs  = o;
    float* out_critic = o + P;
    float* out_vq     = o + P + NB;
    float* out_idx    = o + P + NB + 1;

    static bool inited = false;
    if (!inited) {
        cudaFuncSetAttribute(acsq_kernel,
                             cudaFuncAttributeMaxDynamicSharedMemorySize,
                             SMEM_BYTES);
        inited = true;
    }

    // ONE launch per call -> every ncu -s index lands on the main kernel.
    acsq_kernel<<<NCTA, THREADS, SMEM_BYTES>>>(
        x, W_e0, b_e0, W_e1, b_e1, W_e2, b_e2, W_p, b_p, E,
        W_a0, b_a0, W_a1, b_a1, W_c0, b_c0, W_c1, b_c1, W_c2, b_c2,
        out_probs, out_critic, out_vq, out_idx);
}

// round 12
// speedup vs baseline: 1.0167x; 1.0167x over previous
#include <cuda_runtime.h>
#include <math.h>
#include <stdint.h>

// Problem constants
#define NB      65536
#define FDIM    1024
#define DVQ     64
#define KCODES  512
#define RPC     64
#define NCTA    (NB / RPC)       // 1024
#define THREADS 128

typedef unsigned long long ull;

// Shared-memory layout (float offsets)
//  bufA  [64][132]  activation ping                         8448 fl
//  bufB  [64][132]  activation pong / GEMM1 stage buf0      8448 fl
//        (buf0: Xs0[64][20]=1280 + Ws0[16][192]=3072 = 4352)
//  xqs   [64][68]   VQ projection                           4352 fl
//  stage 4424 fl:   GEMM1 stage buf1 (4352) | chain Wdb[2][16][132]=4224 |
//                   merged Wdb[2][8][264]=4224 | VQ EsT+Enorm+wsum (4424)
#define BUFA_OFF   0
#define BUFB_OFF   (64 * 132)
#define XQ_OFF     (BUFB_OFF + 64 * 132)
#define STAGE_OFF  (XQ_OFF + 64 * 68)
#define STAGE_FL   4424
#define SMEM_BYTES ((STAGE_OFF + STAGE_FL) * 4)   // 102688 B -> 2 CTAs/SM

__device__ float        g_part[NCTA];
__device__ unsigned int g_ctr = 0;

// ---- packed fp32x2 helpers (exact IEEE fp32 per lane, 2x FFMA throughput) ----
__device__ __forceinline__ ull pk2(float a, float b) {
    ull r; asm("mov.b64 %0,{%1,%2};" : "=l"(r) : "f"(a), "f"(b)); return r;
}
__device__ __forceinline__ void ffma2(ull& d, ull a, ull b) {
    asm("fma.rn.f32x2 %0,%1,%2,%3;" : "=l"(d) : "l"(a), "l"(b), "l"(d));
}
__device__ __forceinline__ float2 up2(ull v) {
    float2 f; asm("mov.b64 {%0,%1},%2;" : "=f"(f.x), "=f"(f.y) : "l"(v)); return f;
}

// ---------------------------------------------------------------------------
// 64x128 @ 128x128 chain GEMM. A read directly from smem activations; W
// streamed through a double-buffered 16-row stage with register prefetch
// (LDG -> regs -> compute -> STS -> 1 sync). Thread tx owns cols
// {tx*4 + m*64 | m=0,1} so every W LDS is a contiguous conflict-free 256B.
// Cs may alias As (epilogue writes only after final sync).
// ---------------------------------------------------------------------------
__device__ __forceinline__ void gemm_chain(
    const float* __restrict__ Wg, const float* __restrict__ bias,
    const float* As, float* Cs, float* stage, int tid, bool relu)
{
    const int tx = tid & 15;
    const int ty = tid >> 4;     // rows ty*8 .. ty*8+7
    float* Wdb = stage;          // [2][16*132]
    ull acc[8][4];
#pragma unroll
    for (int i = 0; i < 8; ++i)
#pragma unroll
        for (int j = 0; j < 4; ++j) acc[i][j] = 0ULL;

    // preload chunk 0
#pragma unroll
    for (int t = 0; t < 4; ++t) {
        int idx = tid + t * THREADS;          // 512 float4
        int kk = idx >> 5, q = idx & 31;
        float4 v = *((const float4*)(Wg + (size_t)kk * 128 + q * 4));
        *((float4*)(Wdb + kk * 132 + q * 4)) = v;
    }
    __syncthreads();

    for (int kc = 0; kc < 8; ++kc) {
        const float* Wcur = Wdb + (kc & 1) * (16 * 132);
        float4 wr[4];
        if (kc < 7) {                         // prefetch next chunk into regs
#pragma unroll
            for (int t = 0; t < 4; ++t) {
                int idx = tid + t * THREADS;
                int kk = idx >> 5, q = idx & 31;
                wr[t] = *((const float4*)(Wg + (size_t)((kc + 1) * 16 + kk) * 128 + q * 4));
            }
        }
        const float* Ab = As + ty * 8 * 132 + kc * 16;
#pragma unroll
        for (int kk4 = 0; kk4 < 4; ++kk4) {
            float4 a4[8];
#pragma unroll
            for (int i = 0; i < 8; ++i)
                a4[i] = *((const float4*)(Ab + i * 132 + kk4 * 4));
#pragma unroll
            for (int kkin = 0; kkin < 4; ++kkin) {
                ull pa[8];
#pragma unroll
                for (int i = 0; i < 8; ++i) {
                    float a = ((const float*)&a4[i])[kkin];
                    pa[i] = pk2(a, a);
                }
                const float* wrow = Wcur + (kk4 * 4 + kkin) * 132 + tx * 4;
                ulonglong2 b0 = *((const ulonglong2*)(wrow));
                ulonglong2 b1 = *((const ulonglong2*)(wrow + 64));
                ull b[4] = {b0.x, b0.y, b1.x, b1.y};
#pragma unroll
                for (int i = 0; i < 8; ++i)
#pragma unroll
                    for (int j = 0; j < 4; ++j) ffma2(acc[i][j], pa[i], b[j]);
            }
        }
        if (kc < 7) {                         // store prefetched chunk
            float* Wn = Wdb + ((kc + 1) & 1) * (16 * 132);
#pragma unroll
            for (int t = 0; t < 4; ++t) {
                int idx = tid + t * THREADS;
                int kk = idx >> 5, q = idx & 31;
                *((float4*)(Wn + kk * 132 + q * 4)) = wr[t];
            }
        }
        __syncthreads();
    }
#pragma unroll
    for (int i = 0; i < 8; ++i) {
        int r = ty * 8 + i;
#pragma unroll
        for (int m = 0; m < 2; ++m)
#pragma unroll
            for (int p = 0; p < 2; ++p) {
                float2 v = up2(acc[i][m * 2 + p]);
                int col = m * 64 + tx * 4 + 2 * p;
                float v0 = v.x + bias[col], v1 = v.y + bias[col + 1];
                if (relu) { v0 = fmaxf(v0, 0.f); v1 = fmaxf(v1, 0.f); }
                Cs[r * 132 + col]     = v0;
                Cs[r * 132 + col + 1] = v1;
            }
    }
    __syncthreads();
}

// ---------------------------------------------------------------------------
// Merged 64x128 @ 128x256 GEMM: [a_act | c0] = relu(emb2 @ [W_a0 | W_c0]).
// Same A for both -> one A-read pass, 8x16 thread tile, cols {tx*4 + m*64}.
// Outputs: m=0,1 -> Ca (a_act), m=2,3 -> Cc (c0; may alias As).
// ---------------------------------------------------------------------------
__device__ __forceinline__ void gemm_merged(
    const float* __restrict__ Wa, const float* __restrict__ ba,
    const float* __restrict__ Wc, const float* __restrict__ bc,
    const float* As, float* Ca, float* Cc, float* stage, int tid)
{
    const int tx = tid & 15;
    const int ty = tid >> 4;
    float* Wdb = stage;          // [2][8*264]
    ull acc[8][8];
#pragma unroll
    for (int i = 0; i < 8; ++i)
#pragma unroll
        for (int j = 0; j < 8; ++j) acc[i][j] = 0ULL;

    // preload chunk 0 (8 k-rows x 256 cols)
#pragma unroll
    for (int t = 0; t < 4; ++t) {
        int idx = tid + t * THREADS;          // 512 float4
        int kk = idx >> 6, q = idx & 63;
        int col = q * 4;
        float4 v = (col < 128)
            ? *((const float4*)(Wa + (size_t)kk * 128 + col))
            : *((const float4*)(Wc + (size_t)kk * 128 + col - 128));
        *((float4*)(Wdb + kk * 264 + col)) = v;
    }
    __syncthreads();

    for (int kc = 0; kc < 16; ++kc) {
        const float* Wcur = Wdb + (kc & 1) * (8 * 264);
        float4 wr[4];
        if (kc < 15) {
#pragma unroll
            for (int t = 0; t < 4; ++t) {
                int idx = tid + t * THREADS;
                int kk = idx >> 6, q = idx & 63;
                int col = q * 4;
                int krow = (kc + 1) * 8 + kk;
                wr[t] = (col < 128)
                    ? *((const float4*)(Wa + (size_t)krow * 128 + col))
                    : *((const float4*)(Wc + (size_t)krow * 128 + col - 128));
            }
        }
        const float* Ab = As + ty * 8 * 132 + kc * 8;
#pragma unroll
        for (int kk4 = 0; kk4 < 2; ++kk4) {
            float4 a4[8];
#pragma unroll
            for (int i = 0; i < 8; ++i)
                a4[i] = *((const float4*)(Ab + i * 132 + kk4 * 4));
#pragma unroll
            for (int kkin = 0; kkin < 4; ++kkin) {
                ull pa[8];
#pragma unroll
                for (int i = 0; i < 8; ++i) {
                    float a = ((const float*)&a4[i])[kkin];
                    pa[i] = pk2(a, a);
                }
                const float* wrow = Wcur + (kk4 * 4 + kkin) * 264 + tx * 4;
                ulonglong2 q0 = *((const ulonglong2*)(wrow));
                ulonglong2 q1 = *((const ulonglong2*)(wrow + 64));
                ulonglong2 q2 = *((const ulonglong2*)(wrow + 128));
                ulonglong2 q3 = *((const ulonglong2*)(wrow + 192));
                ull b[8] = {q0.x, q0.y, q1.x, q1.y, q2.x, q2.y, q3.x, q3.y};
#pragma unroll
                for (int i = 0; i < 8; ++i)
#pragma unroll
                    for (int j = 0; j < 8; ++j) ffma2(acc[i][j], pa[i], b[j]);
            }
        }
        if (kc < 15) {
            float* Wn = Wdb + ((kc + 1) & 1) * (8 * 264);
#pragma unroll
            for (int t = 0; t < 4; ++t) {
                int idx = tid + t * THREADS;
                int kk = idx >> 6, q = idx & 63;
                *((float4*)(Wn + kk * 264 + q * 4)) = wr[t];
            }
        }
        __syncthreads();
    }
#pragma unroll
    for (int i = 0; i < 8; ++i) {
        int r = ty * 8 + i;
#pragma unroll
        for (int m = 0; m < 4; ++m)
#pragma unroll
            for (int p = 0; p < 2; ++p) {
                float2 v = up2(acc[i][m * 2 + p]);
                int col = m * 64 + tx * 4 + 2 * p;
                if (m < 2) {
                    Ca[r * 132 + col]     = fmaxf(v.x + ba[col], 0.f);
                    Ca[r * 132 + col + 1] = fmaxf(v.y + ba[col + 1], 0.f);
                } else {
                    int cc = col - 128;
                    Cc[r * 132 + cc]     = fmaxf(v.x + bc[cc], 0.f);
                    Cc[r * 132 + cc + 1] = fmaxf(v.y + bc[cc + 1], 0.f);
                }
            }
    }
    __syncthreads();
}

// ---------------------------------------------------------------------------
// Single fused kernel: one CTA = 64 batch rows end-to-end; last CTA finishes
// the vq_loss reduction (one launch per call).
// ---------------------------------------------------------------------------
extern __shared__ float smem[];

__global__ void __launch_bounds__(THREADS, 2)
acsq_kernel(const float* __restrict__ x,
            const float* __restrict__ W_e0, const float* __restrict__ b_e0,
            const float* __restrict__ W_e1, const float* __restrict__ b_e1,
            const float* __restrict__ W_e2, const float* __restrict__ b_e2,
            const float* __restrict__ W_p,  const float* __restrict__ b_p,
            const float* __restrict__ E,
            const float* __restrict__ W_a0, const float* __restrict__ b_a0,
            const float* __restrict__ W_a1, const float* __restrict__ b_a1,
            const float* __restrict__ W_c0, const float* __restrict__ b_c0,
            const float* __restrict__ W_c1, const float* __restrict__ b_c1,
            const float* __restrict__ W_c2, const float* __restrict__ b_c2,
            float* __restrict__ out_probs, float* __restrict__ out_critic,
            float* __restrict__ out_vq,    float* __restrict__ out_idx)
{
    float* bufA  = smem + BUFA_OFF;
    float* bufB  = smem + BUFB_OFF;
    float* xqs   = smem + XQ_OFF;
    float* stage = smem + STAGE_OFF;
    const int tid  = threadIdx.x;
    const int row0 = blockIdx.x * RPC;

    // ============== GEMM1: X[64x1024] @ [W_e0 | W_p] [1024x192] ==============
    // Double-buffered K=16 chunks: buf0 in bufB, buf1 in stage. Thread tile
    // 8 rows x 12 cols as {tx*4 + m*64 | m=0,1,2}: m<2 -> emb0, m=2 -> xq.
    {
        const int tx = tid & 15;
        const int ty = tid >> 4;
        float* Xs0 = bufB;               // [64][20]
        float* Ws0 = bufB + 1280;        // [16][192]
        float* Xs1 = stage;
        float* Ws1 = stage + 1280;
        ull acc[8][6];
#pragma unroll
        for (int i = 0; i < 8; ++i)
#pragma unroll
            for (int j = 0; j < 6; ++j) acc[i][j] = 0ULL;

        // preload chunk 0 into buf0
#pragma unroll
        for (int t = 0; t < 2; ++t) {
            int idx = tid + t * THREADS;          // 256 float4
            int r = idx >> 2, q = idx & 3;
            float4 v = *((const float4*)(x + (size_t)(row0 + r) * FDIM + q * 4));
            *((float4*)(Xs0 + r * 20 + q * 4)) = v;
        }
#pragma unroll
        for (int t = 0; t < 6; ++t) {
            int idx = tid + t * THREADS;          // 768 float4
            int kk = idx / 48, q = idx % 48;
            float4 v = (q < 32)
                ? *((const float4*)(W_e0 + (size_t)kk * 128 + q * 4))
                : *((const float4*)(W_p  + (size_t)kk * 64 + (q - 32) * 4));
            *((float4*)(Ws0 + kk * 192 + q * 4)) = v;
        }
        __syncthreads();

        for (int kc = 0; kc < 64; ++kc) {
            const float* Xc = (kc & 1) ? Xs1 : Xs0;
            const float* Wc = (kc & 1) ? Ws1 : Ws0;
            float4 xr[2], wr[6];
            if (kc < 63) {                        // prefetch next chunk to regs
                int k0 = (kc + 1) * 16;
#pragma unroll
                for (int t = 0; t < 2; ++t) {
                    int idx = tid + t * THREADS;
                    int r = idx >> 2, q = idx & 3;
                    xr[t] = *((const float4*)(x + (size_t)(row0 + r) * FDIM + k0 + q * 4));
                }
#pragma unroll
                for (int t = 0; t < 6; ++t) {
                    int idx = tid + t * THREADS;
                    int kk = idx / 48, q = idx % 48;
                    int krow = k0 + kk;
                    wr[t] = (q < 32)
                        ? *((const float4*)(W_e0 + (size_t)krow * 128 + q * 4))
                        : *((const float4*)(W_p  + (size_t)krow * 64 + (q - 32) * 4));
                }
            }
            const float* Xb = Xc + ty * 8 * 20;
#pragma unroll
            for (int kk4 = 0; kk4 < 4; ++kk4) {
                float4 a4[8];
#pragma unroll
                for (int i = 0; i < 8; ++i)
                    a4[i] = *((const float4*)(Xb + i * 20 + kk4 * 4));
#pragma unroll
                for (int kkin = 0; kkin < 4; ++kkin) {
                    ull pa[8];
#pragma unroll
                    for (int i = 0; i < 8; ++i) {
                        float a = ((const float*)&a4[i])[kkin];
                        pa[i] = pk2(a, a);
                    }
                    const float* wrow = Wc + (kk4 * 4 + kkin) * 192 + tx * 4;
                    ulonglong2 q0 = *((const ulonglong2*)(wrow));
                    ulonglong2 q1 = *((const ulonglong2*)(wrow + 64));
                    ulonglong2 q2 = *((const ulonglong2*)(wrow + 128));
                    ull b[6] = {q0.x, q0.y, q1.x, q1.y, q2.x, q2.y};
#pragma unroll
                    for (int i = 0; i < 8; ++i)
#pragma unroll
                        for (int j = 0; j < 6; ++j) ffma2(acc[i][j], pa[i], b[j]);
                }
            }
            if (kc < 63) {                        // store prefetched chunk
                float* Xn = (kc & 1) ? Xs0 : Xs1;
                float* Wn = (kc & 1) ? Ws0 : Ws1;
#pragma unroll
                for (int t = 0; t < 2; ++t) {
                    int idx = tid + t * THREADS;
                    int r = idx >> 2, q = idx & 3;
                    *((float4*)(Xn + r * 20 + q * 4)) = xr[t];
                }
#pragma unroll
                for (int t = 0; t < 6; ++t) {
                    int idx = tid + t * THREADS;
                    int kk = idx / 48, q = idx % 48;
                    *((float4*)(Wn + kk * 192 + q * 4)) = wr[t];
                }
            }
            __syncthreads();
        }
        // Epilogue: m<2 -> emb0 = relu(+b_e0) -> bufA; m=2 -> xq (+b_p) -> xqs
#pragma unroll
        for (int i = 0; i < 8; ++i) {
            int r = ty * 8 + i;
#pragma unroll
            for (int m = 0; m < 3; ++m)
#pragma unroll
                for (int p = 0; p < 2; ++p) {
                    float2 v = up2(acc[i][m * 2 + p]);
                    int col = m * 64 + tx * 4 + 2 * p;
                    if (m < 2) {
                        bufA[r * 132 + col]     = fmaxf(v.x + b_e0[col], 0.f);
                        bufA[r * 132 + col + 1] = fmaxf(v.y + b_e0[col + 1], 0.f);
                    } else {
                        int cq = col - 128;
                        xqs[r * 68 + cq]     = v.x + b_p[cq];
                        xqs[r * 68 + cq + 1] = v.y + b_p[cq + 1];
                    }
                }
        }
        __syncthreads();
    }

    // ============== VQ: argmin_k (||E_k||^2 - 2 xq.E_k), e_latent partials ===
    {
        float* EsT   = stage;                // [64 d][68] transposed codes
        float* Enorm = stage + 64 * 68;      // [64]
        float* wsum  = stage + 64 * 68 + 64; // [4]
        const int cg = tid & 7;              // code subgroup: codes cg*8..cg*8+7
        const int rg = tid >> 3;             // 0..15
        const int r0 = rg * 4;               // 4 rows per thread
        float best[4]; int bidx[4];
#pragma unroll
        for (int i = 0; i < 4; ++i) { best[i] = 3.402823e38f; bidx[i] = 0; }

        for (int cc = 0; cc < 8; ++cc) {
#pragma unroll
            for (int t = 0; t < 8; ++t) {
                int idx = tid + t * THREADS;
                int dq = idx >> 6, c = idx & 63;
                float4 v = *((const float4*)(E + (size_t)(cc * 64 + c) * DVQ + dq * 4));
                EsT[(dq * 4 + 0) * 68 + c] = v.x;
                EsT[(dq * 4 + 1) * 68 + c] = v.y;
                EsT[(dq * 4 + 2) * 68 + c] = v.z;
                EsT[(dq * 4 + 3) * 68 + c] = v.w;
            }
            __syncthreads();
            if (tid < 64) {
                float s = 0.f;
#pragma unroll 8
                for (int d = 0; d < DVQ; ++d) { float e = EsT[d * 68 + tid]; s = fmaf(e, e, s); }
                Enorm[tid] = s;
            }
            __syncthreads();

            ull acc[4][4];
#pragma unroll
            for (int i = 0; i < 4; ++i)
#pragma unroll
                for (int j = 0; j < 4; ++j) acc[i][j] = 0ULL;

#pragma unroll
            for (int d4 = 0; d4 < 16; ++d4) {
                float4 a4[4];
#pragma unroll
                for (int i = 0; i < 4; ++i)
                    a4[i] = *((const float4*)(xqs + (r0 + i) * 68 + d4 * 4));
#pragma unroll
                for (int din = 0; din < 4; ++din) {
                    ull pa[4];
#pragma unroll
                    for (int i = 0; i < 4; ++i) {
                        float a = ((const float*)&a4[i])[din];
                        pa[i] = pk2(a, a);
                    }
                    const ulonglong2* bp =
                        (const ulonglong2*)(EsT + (d4 * 4 + din) * 68 + cg * 8);
                    ulonglong2 b01 = bp[0], b23 = bp[1];
                    ull b[4] = {b01.x, b01.y, b23.x, b23.y};
#pragma unroll
                    for (int i = 0; i < 4; ++i)
#pragma unroll
                        for (int j = 0; j < 4; ++j) ffma2(acc[i][j], pa[i], b[j]);
                }
            }
#pragma unroll
            for (int j = 0; j < 4; ++j) {
                int c0 = cg * 8 + 2 * j;
                float n0 = Enorm[c0], n1 = Enorm[c0 + 1];
                int g0 = cc * 64 + c0;
#pragma unroll
                for (int i = 0; i < 4; ++i) {
                    float2 dv = up2(acc[i][j]);
                    float s;
                    s = fmaf(-2.f, dv.x, n0); if (s < best[i]) { best[i] = s; bidx[i] = g0; }
                    s = fmaf(-2.f, dv.y, n1); if (s < best[i]) { best[i] = s; bidx[i] = g0 + 1; }
                }
            }
            __syncthreads();
        }
#pragma unroll
        for (int i = 0; i < 4; ++i) {
            float v = best[i]; int bi = bidx[i];
#pragma unroll
            for (int o = 1; o <= 4; o <<= 1) {
                float ov = __shfl_xor_sync(0xffffffffu, v, o);
                int   oi = __shfl_xor_sync(0xffffffffu, bi, o);
                if (ov < v || (ov == v && oi < bi)) { v = ov; bi = oi; }
            }
            best[i] = v; bidx[i] = bi;
        }
        float s_lat = 0.f;
        if (cg == 0) {
#pragma unroll
            for (int i = 0; i < 4; ++i) {
                int r = r0 + i;
                out_idx[row0 + r] = (float)bidx[i];
                const float* e = E + (size_t)bidx[i] * DVQ;
                float s = 0.f;
#pragma unroll 8
                for (int d = 0; d < DVQ; ++d) {
                    float diff = e[d] - xqs[r * 68 + d];
                    s = fmaf(diff, diff, s);
                }
                s_lat += s;
            }
        }
#pragma unroll
        for (int o = 16; o >= 1; o >>= 1)
            s_lat += __shfl_xor_sync(0xffffffffu, s_lat, o);
        if ((tid & 31) == 0) wsum[tid >> 5] = s_lat;
        __syncthreads();
        if (tid == 0) {
            float t = 0.f;
#pragma unroll
            for (int w = 0; w < 4; ++w) t += wsum[w];
            g_part[blockIdx.x] = t;
        }
        __syncthreads();   // stage reused by chain GEMMs below
    }

    // ============== MLP chain (activations resident in smem) =================
    // bufA = emb0
    gemm_chain(W_e1, b_e1, bufA, bufB, stage, tid, true);     // emb1 -> bufB
    gemm_chain(W_e2, b_e2, bufB, bufA, stage, tid, true);     // emb2 -> bufA
    gemm_merged(W_a0, b_a0, W_c0, b_c0, bufA, bufB, bufA,     // a_act -> bufB,
                stage, tid);                                  // c0 -> bufA
    gemm_chain(W_a1, b_a1, bufB, bufB, stage, tid, false);    // logits -> bufB
    gemm_chain(W_c1, b_c1, bufA, bufA, stage, tid, true);     // c1 -> bufA

    // ============== critic weight stage + softmax ============================
    stage[tid] = W_c2[tid];   // 128 threads = 128 weights

    {   // softmax over bufB rows -> out_probs
        int warp = tid >> 5, lane = tid & 31;
        for (int r = warp; r < RPC; r += 4) {
            float4 v = *((float4*)(bufB + r * 132 + lane * 4));
            float m = fmaxf(fmaxf(v.x, v.y), fmaxf(v.z, v.w));
#pragma unroll
            for (int o = 16; o >= 1; o >>= 1)
                m = fmaxf(m, __shfl_xor_sync(0xffffffffu, m, o));
            float e0 = expf(v.x - m), e1 = expf(v.y - m);
            float e2 = expf(v.z - m), e3 = expf(v.w - m);
            float s = (e0 + e1) + (e2 + e3);
#pragma unroll
            for (int o = 16; o >= 1; o >>= 1)
                s += __shfl_xor_sync(0xffffffffu, s, o);
            float4 p = make_float4(e0 / s, e1 / s, e2 / s, e3 / s);
            *((float4*)(out_probs + (size_t)(row0 + r) * 128 + lane * 4)) = p;
        }
    }
    __syncthreads();

    // ============== critic head: c1 @ W_c2 + b_c2 ============================
    if (tid < RPC) {
        float dotv = 0.f;
#pragma unroll 8
        for (int d = 0; d < 128; ++d)
            dotv = fmaf(bufA[tid * 132 + d], stage[d], dotv);
        out_critic[row0 + tid] = dotv + b_c2[0];
    }
    __syncthreads();

    // ============== last-CTA vq_loss finalize (single-launch design) =========
    __threadfence();
    unsigned int* flag = (unsigned int*)stage;
    if (tid == 0) {
        unsigned int p = atomicAdd(&g_ctr, 1u);
        flag[0] = (p == NCTA - 1) ? 1u : 0u;
    }
    __syncthreads();
    if (flag[0]) {
        float s = 0.f;
        for (int i = tid; i < NCTA; i += THREADS) s += g_part[i];
#pragma unroll
        for (int o = 16; o >= 1; o >>= 1)
            s += __shfl_xor_sync(0xffffffffu, s, o);
        if ((tid & 31) == 0) stage[8 + (tid >> 5)] = s;
        __syncthreads();
        if (tid == 0) {
            float t = 0.f;
#pragma unroll
            for (int w = 0; w < 4; ++w) t += stage[8 + w];
            out_vq[0] = (float)((double)t * (1.25 / ((double)NB * (double)DVQ)));
            g_ctr = 0;   // reset for next graph replay
        }
    }
}

// ---------------------------------------------------------------------------
extern "C" void kernel_launch(void* const* d_in, const int* in_sizes, int n_in,
                              void* d_out, int out_size)
{
    const float* x    = (const float*)d_in[0];
    const float* W_e0 = (const float*)d_in[1];
    const float* b_e0 = (const float*)d_in[2];
    const float* W_e1 = (const float*)d_in[3];
    const float* b_e1 = (const float*)d_in[4];
    const float* W_e2 = (const float*)d_in[5];
    const float* b_e2 = (const float*)d_in[6];
    const float* W_p  = (const float*)d_in[7];
    const float* b_p  = (const float*)d_in[8];
    const float* E    = (const float*)d_in[9];
    const float* W_a0 = (const float*)d_in[10];
    const float* b_a0 = (const float*)d_in[11];
    const float* W_a1 = (const float*)d_in[12];
    const float* b_a1 = (const float*)d_in[13];
    const float* W_c0 = (const float*)d_in[14];
    const float* b_c0 = (const float*)d_in[15];
    const float* W_c1 = (const float*)d_in[16];
    const float* b_c1 = (const float*)d_in[17];
    const float* W_c2 = (const float*)d_in[18];
    const float* b_c2 = (const float*)d_in[19];

    float* o = (float*)d_out;
    const size_t P = (size_t)NB * 128;
    float* out_probs  = o;
    float* out_critic = o + P;
    float* out_vq     = o + P + NB;
    float* out_idx    = o + P + NB + 1;

    static bool inited = false;
    if (!inited) {
        cudaFuncSetAttribute(acsq_kernel,
                             cudaFuncAttributeMaxDynamicSharedMemorySize,
                             SMEM_BYTES);
        inited = true;
    }

    // ONE launch per call -> every ncu -s index lands on the main kernel.
    acsq_kernel<<<NCTA, THREADS, SMEM_BYTES>>>(
        x, W_e0, b_e0, W_e1, b_e1, W_e2, b_e2, W_p, b_p, E,
        W_a0, b_a0, W_a1, b_a1, W_c0, b_c0, W_c1, b_c1, W_c2, b_c2,
        out_probs, out_critic, out_vq, out_idx);
}

// round 13
// speedup vs baseline: 1.0174x; 1.0007x over previous
#include <cuda_runtime.h>
#include <math.h>
#include <stdint.h>

// Problem constants
#define NB      65536
#define FDIM    1024
#define DVQ     64
#define KCODES  512
#define RPC     64
#define NCTA    (NB / RPC)       // 1024
#define THREADS 128

typedef unsigned long long ull;

// Shared-memory layout (float offsets)
//  bufA  [64][132]  activation ping                         8448 fl
//  bufB  [64][132]  activation pong / GEMM1 stage buf0      8448 fl
//        (buf0: Xs0[64][20]=1280 + Ws0[16][192]=3072 = 4352)
//  xqs   [64][68]   VQ projection                           4352 fl
//  stage 4424 fl:   GEMM1 stage buf1 (4352) | chain Wdb[2][16][132]=4224 |
//                   merged Wdb[2][8][264]=4224 | VQ EsT+Enorm+wsum (4424)
#define BUFA_OFF   0
#define BUFB_OFF   (64 * 132)
#define XQ_OFF     (BUFB_OFF + 64 * 132)
#define STAGE_OFF  (XQ_OFF + 64 * 68)
#define STAGE_FL   4424
#define SMEM_BYTES ((STAGE_OFF + STAGE_FL) * 4)   // 102688 B -> 2 CTAs/SM

__device__ float        g_part[NCTA];
__device__ unsigned int g_ctr = 0;

// ---- packed fp32x2 helpers (exact IEEE fp32 per lane, 2x FFMA throughput) ----
__device__ __forceinline__ ull pk2(float a, float b) {
    ull r; asm("mov.b64 %0,{%1,%2};" : "=l"(r) : "f"(a), "f"(b)); return r;
}
__device__ __forceinline__ void ffma2(ull& d, ull a, ull b) {
    asm("fma.rn.f32x2 %0,%1,%2,%3;" : "=l"(d) : "l"(a), "l"(b), "l"(d));
}
__device__ __forceinline__ float2 up2(ull v) {
    float2 f; asm("mov.b64 {%0,%1},%2;" : "=f"(f.x), "=f"(f.y) : "l"(v)); return f;
}

// ---------------------------------------------------------------------------
// 64x128 @ 128x128 chain GEMM. A read directly from smem activations; W
// streamed through a double-buffered 16-row stage with register prefetch
// (LDG -> regs -> compute -> STS -> 1 sync). Thread tx owns cols
// {tx*4 + m*64 | m=0,1} so every W LDS is a contiguous conflict-free 256B.
// Cs may alias As (epilogue writes only after final sync).
// ---------------------------------------------------------------------------
__device__ __forceinline__ void gemm_chain(
    const float* __restrict__ Wg, const float* __restrict__ bias,
    const float* As, float* Cs, float* stage, int tid, bool relu)
{
    const int tx = tid & 15;
    const int ty = tid >> 4;     // rows ty*8 .. ty*8+7
    float* Wdb = stage;          // [2][16*132]
    ull acc[8][4];
#pragma unroll
    for (int i = 0; i < 8; ++i)
#pragma unroll
        for (int j = 0; j < 4; ++j) acc[i][j] = 0ULL;

    // preload chunk 0
#pragma unroll
    for (int t = 0; t < 4; ++t) {
        int idx = tid + t * THREADS;          // 512 float4
        int kk = idx >> 5, q = idx & 31;
        float4 v = *((const float4*)(Wg + (size_t)kk * 128 + q * 4));
        *((float4*)(Wdb + kk * 132 + q * 4)) = v;
    }
    __syncthreads();

    for (int kc = 0; kc < 8; ++kc) {
        const float* Wcur = Wdb + (kc & 1) * (16 * 132);
        float4 wr[4];
        if (kc < 7) {                         // prefetch next chunk into regs
#pragma unroll
            for (int t = 0; t < 4; ++t) {
                int idx = tid + t * THREADS;
                int kk = idx >> 5, q = idx & 31;
                wr[t] = *((const float4*)(Wg + (size_t)((kc + 1) * 16 + kk) * 128 + q * 4));
            }
        }
        const float* Ab = As + ty * 8 * 132 + kc * 16;
#pragma unroll
        for (int kk4 = 0; kk4 < 4; ++kk4) {
            float4 a4[8];
#pragma unroll
            for (int i = 0; i < 8; ++i)
                a4[i] = *((const float4*)(Ab + i * 132 + kk4 * 4));
#pragma unroll
            for (int kkin = 0; kkin < 4; ++kkin) {
                ull pa[8];
#pragma unroll
                for (int i = 0; i < 8; ++i) {
                    float a = ((const float*)&a4[i])[kkin];
                    pa[i] = pk2(a, a);
                }
                const float* wrow = Wcur + (kk4 * 4 + kkin) * 132 + tx * 4;
                ulonglong2 b0 = *((const ulonglong2*)(wrow));
                ulonglong2 b1 = *((const ulonglong2*)(wrow + 64));
                ull b[4] = {b0.x, b0.y, b1.x, b1.y};
#pragma unroll
                for (int i = 0; i < 8; ++i)
#pragma unroll
                    for (int j = 0; j < 4; ++j) ffma2(acc[i][j], pa[i], b[j]);
            }
        }
        if (kc < 7) {                         // store prefetched chunk
            float* Wn = Wdb + ((kc + 1) & 1) * (16 * 132);
#pragma unroll
            for (int t = 0; t < 4; ++t) {
                int idx = tid + t * THREADS;
                int kk = idx >> 5, q = idx & 31;
                *((float4*)(Wn + kk * 132 + q * 4)) = wr[t];
            }
        }
        __syncthreads();
    }
#pragma unroll
    for (int i = 0; i < 8; ++i) {
        int r = ty * 8 + i;
#pragma unroll
        for (int m = 0; m < 2; ++m)
#pragma unroll
            for (int p = 0; p < 2; ++p) {
                float2 v = up2(acc[i][m * 2 + p]);
                int col = m * 64 + tx * 4 + 2 * p;
                float v0 = v.x + bias[col], v1 = v.y + bias[col + 1];
                if (relu) { v0 = fmaxf(v0, 0.f); v1 = fmaxf(v1, 0.f); }
                Cs[r * 132 + col]     = v0;
                Cs[r * 132 + col + 1] = v1;
            }
    }
    __syncthreads();
}

// ---------------------------------------------------------------------------
// Merged 64x128 @ 128x256 GEMM: [a_act | c0] = relu(emb2 @ [W_a0 | W_c0]).
// Same A for both -> one A-read pass, 8x16 thread tile, cols {tx*4 + m*64}.
// Outputs: m=0,1 -> Ca (a_act), m=2,3 -> Cc (c0; may alias As).
// ---------------------------------------------------------------------------
__device__ __forceinline__ void gemm_merged(
    const float* __restrict__ Wa, const float* __restrict__ ba,
    const float* __restrict__ Wc, const float* __restrict__ bc,
    const float* As, float* Ca, float* Cc, float* stage, int tid)
{
    const int tx = tid & 15;
    const int ty = tid >> 4;
    float* Wdb = stage;          // [2][8*264]
    ull acc[8][8];
#pragma unroll
    for (int i = 0; i < 8; ++i)
#pragma unroll
        for (int j = 0; j < 8; ++j) acc[i][j] = 0ULL;

    // preload chunk 0 (8 k-rows x 256 cols)
#pragma unroll
    for (int t = 0; t < 4; ++t) {
        int idx = tid + t * THREADS;          // 512 float4
        int kk = idx >> 6, q = idx & 63;
        int col = q * 4;
        float4 v = (col < 128)
            ? *((const float4*)(Wa + (size_t)kk * 128 + col))
            : *((const float4*)(Wc + (size_t)kk * 128 + col - 128));
        *((float4*)(Wdb + kk * 264 + col)) = v;
    }
    __syncthreads();

    for (int kc = 0; kc < 16; ++kc) {
        const float* Wcur = Wdb + (kc & 1) * (8 * 264);
        float4 wr[4];
        if (kc < 15) {
#pragma unroll
            for (int t = 0; t < 4; ++t) {
                int idx = tid + t * THREADS;
                int kk = idx >> 6, q = idx & 63;
                int col = q * 4;
                int krow = (kc + 1) * 8 + kk;
                wr[t] = (col < 128)
                    ? *((const float4*)(Wa + (size_t)krow * 128 + col))
                    : *((const float4*)(Wc + (size_t)krow * 128 + col - 128));
            }
        }
        const float* Ab = As + ty * 8 * 132 + kc * 8;
#pragma unroll
        for (int kk4 = 0; kk4 < 2; ++kk4) {
            float4 a4[8];
#pragma unroll
            for (int i = 0; i < 8; ++i)
                a4[i] = *((const float4*)(Ab + i * 132 + kk4 * 4));
#pragma unroll
            for (int kkin = 0; kkin < 4; ++kkin) {
                ull pa[8];
#pragma unroll
                for (int i = 0; i < 8; ++i) {
                    float a = ((const float*)&a4[i])[kkin];
                    pa[i] = pk2(a, a);
                }
                const float* wrow = Wcur + (kk4 * 4 + kkin) * 264 + tx * 4;
                ulonglong2 q0 = *((const ulonglong2*)(wrow));
                ulonglong2 q1 = *((const ulonglong2*)(wrow + 64));
                ulonglong2 q2 = *((const ulonglong2*)(wrow + 128));
                ulonglong2 q3 = *((const ulonglong2*)(wrow + 192));
                ull b[8] = {q0.x, q0.y, q1.x, q1.y, q2.x, q2.y, q3.x, q3.y};
#pragma unroll
                for (int i = 0; i < 8; ++i)
#pragma unroll
                    for (int j = 0; j < 8; ++j) ffma2(acc[i][j], pa[i], b[j]);
            }
        }
        if (kc < 15) {
            float* Wn = Wdb + ((kc + 1) & 1) * (8 * 264);
#pragma unroll
            for (int t = 0; t < 4; ++t) {
                int idx = tid + t * THREADS;
                int kk = idx >> 6, q = idx & 63;
                *((float4*)(Wn + kk * 264 + q * 4)) = wr[t];
            }
        }
        __syncthreads();
    }
#pragma unroll
    for (int i = 0; i < 8; ++i) {
        int r = ty * 8 + i;
#pragma unroll
        for (int m = 0; m < 4; ++m)
#pragma unroll
            for (int p = 0; p < 2; ++p) {
                float2 v = up2(acc[i][m * 2 + p]);
                int col = m * 64 + tx * 4 + 2 * p;
                if (m < 2) {
                    Ca[r * 132 + col]     = fmaxf(v.x + ba[col], 0.f);
                    Ca[r * 132 + col + 1] = fmaxf(v.y + ba[col + 1], 0.f);
                } else {
                    int cc = col - 128;
                    Cc[r * 132 + cc]     = fmaxf(v.x + bc[cc], 0.f);
                    Cc[r * 132 + cc + 1] = fmaxf(v.y + bc[cc + 1], 0.f);
                }
            }
    }
    __syncthreads();
}

// ---------------------------------------------------------------------------
// Single fused kernel: one CTA = 64 batch rows end-to-end; last CTA finishes
// the vq_loss reduction (one launch per call).
// ---------------------------------------------------------------------------
extern __shared__ float smem[];

__global__ void __launch_bounds__(THREADS, 2)
acsq_kernel(const float* __restrict__ x,
            const float* __restrict__ W_e0, const float* __restrict__ b_e0,
            const float* __restrict__ W_e1, const float* __restrict__ b_e1,
            const float* __restrict__ W_e2, const float* __restrict__ b_e2,
            const float* __restrict__ W_p,  const float* __restrict__ b_p,
            const float* __restrict__ E,
            const float* __restrict__ W_a0, const float* __restrict__ b_a0,
            const float* __restrict__ W_a1, const float* __restrict__ b_a1,
            const float* __restrict__ W_c0, const float* __restrict__ b_c0,
            const float* __restrict__ W_c1, const float* __restrict__ b_c1,
            const float* __restrict__ W_c2, const float* __restrict__ b_c2,
            float* __restrict__ out_probs, float* __restrict__ out_critic,
            float* __restrict__ out_vq,    float* __restrict__ out_idx)
{
    float* bufA  = smem + BUFA_OFF;
    float* bufB  = smem + BUFB_OFF;
    float* xqs   = smem + XQ_OFF;
    float* stage = smem + STAGE_OFF;
    const int tid  = threadIdx.x;
    const int row0 = blockIdx.x * RPC;

    // ============== GEMM1: X[64x1024] @ [W_e0 | W_p] [1024x192] ==============
    // Double-buffered K=16 chunks: buf0 in bufB, buf1 in stage. Thread tile
    // 8 rows x 12 cols as {tx*4 + m*64 | m=0,1,2}: m<2 -> emb0, m=2 -> xq.
    {
        const int tx = tid & 15;
        const int ty = tid >> 4;
        float* Xs0 = bufB;               // [64][20]
        float* Ws0 = bufB + 1280;        // [16][192]
        float* Xs1 = stage;
        float* Ws1 = stage + 1280;
        ull acc[8][6];
#pragma unroll
        for (int i = 0; i < 8; ++i)
#pragma unroll
            for (int j = 0; j < 6; ++j) acc[i][j] = 0ULL;

        // preload chunk 0 into buf0
#pragma unroll
        for (int t = 0; t < 2; ++t) {
            int idx = tid + t * THREADS;          // 256 float4
            int r = idx >> 2, q = idx & 3;
            float4 v = *((const float4*)(x + (size_t)(row0 + r) * FDIM + q * 4));
            *((float4*)(Xs0 + r * 20 + q * 4)) = v;
        }
#pragma unroll
        for (int t = 0; t < 6; ++t) {
            int idx = tid + t * THREADS;          // 768 float4
            int kk = idx / 48, q = idx % 48;
            float4 v = (q < 32)
                ? *((const float4*)(W_e0 + (size_t)kk * 128 + q * 4))
                : *((const float4*)(W_p  + (size_t)kk * 64 + (q - 32) * 4));
            *((float4*)(Ws0 + kk * 192 + q * 4)) = v;
        }
        __syncthreads();

        for (int kc = 0; kc < 64; ++kc) {
            const float* Xc = (kc & 1) ? Xs1 : Xs0;
            const float* Wc = (kc & 1) ? Ws1 : Ws0;
            float4 xr[2], wr[6];
            if (kc < 63) {                        // prefetch next chunk to regs
                int k0 = (kc + 1) * 16;
#pragma unroll
                for (int t = 0; t < 2; ++t) {
                    int idx = tid + t * THREADS;
                    int r = idx >> 2, q = idx & 3;
                    xr[t] = *((const float4*)(x + (size_t)(row0 + r) * FDIM + k0 + q * 4));
                }
#pragma unroll
                for (int t = 0; t < 6; ++t) {
                    int idx = tid + t * THREADS;
                    int kk = idx / 48, q = idx % 48;
                    int krow = k0 + kk;
                    wr[t] = (q < 32)
                        ? *((const float4*)(W_e0 + (size_t)krow * 128 + q * 4))
                        : *((const float4*)(W_p  + (size_t)krow * 64 + (q - 32) * 4));
                }
            }
            const float* Xb = Xc + ty * 8 * 20;
#pragma unroll
            for (int kk4 = 0; kk4 < 4; ++kk4) {
                float4 a4[8];
#pragma unroll
                for (int i = 0; i < 8; ++i)
                    a4[i] = *((const float4*)(Xb + i * 20 + kk4 * 4));
#pragma unroll
                for (int kkin = 0; kkin < 4; ++kkin) {
                    ull pa[8];
#pragma unroll
                    for (int i = 0; i < 8; ++i) {
                        float a = ((const float*)&a4[i])[kkin];
                        pa[i] = pk2(a, a);
                    }
                    const float* wrow = Wc + (kk4 * 4 + kkin) * 192 + tx * 4;
                    ulonglong2 q0 = *((const ulonglong2*)(wrow));
                    ulonglong2 q1 = *((const ulonglong2*)(wrow + 64));
                    ulonglong2 q2 = *((const ulonglong2*)(wrow + 128));
                    ull b[6] = {q0.x, q0.y, q1.x, q1.y, q2.x, q2.y};
#pragma unroll
                    for (int i = 0; i < 8; ++i)
#pragma unroll
                        for (int j = 0; j < 6; ++j) ffma2(acc[i][j], pa[i], b[j]);
                }
            }
            if (kc < 63) {                        // store prefetched chunk
                float* Xn = (kc & 1) ? Xs0 : Xs1;
                float* Wn = (kc & 1) ? Ws0 : Ws1;
#pragma unroll
                for (int t = 0; t < 2; ++t) {
                    int idx = tid + t * THREADS;
                    int r = idx >> 2, q = idx & 3;
                    *((float4*)(Xn + r * 20 + q * 4)) = xr[t];
                }
#pragma unroll
                for (int t = 0; t < 6; ++t) {
                    int idx = tid + t * THREADS;
                    int kk = idx / 48, q = idx % 48;
                    *((float4*)(Wn + kk * 192 + q * 4)) = wr[t];
                }
            }
            __syncthreads();
        }
        // Epilogue: m<2 -> emb0 = relu(+b_e0) -> bufA; m=2 -> xq (+b_p) -> xqs
#pragma unroll
        for (int i = 0; i < 8; ++i) {
            int r = ty * 8 + i;
#pragma unroll
            for (int m = 0; m < 3; ++m)
#pragma unroll
                for (int p = 0; p < 2; ++p) {
                    float2 v = up2(acc[i][m * 2 + p]);
                    int col = m * 64 + tx * 4 + 2 * p;
                    if (m < 2) {
                        bufA[r * 132 + col]     = fmaxf(v.x + b_e0[col], 0.f);
                        bufA[r * 132 + col + 1] = fmaxf(v.y + b_e0[col + 1], 0.f);
                    } else {
                        int cq = col - 128;
                        xqs[r * 68 + cq]     = v.x + b_p[cq];
                        xqs[r * 68 + cq + 1] = v.y + b_p[cq + 1];
                    }
                }
        }
        __syncthreads();
    }

    // ============== VQ: argmin_k (||E_k||^2 - 2 xq.E_k), e_latent partials ===
    {
        float* EsT   = stage;                // [64 d][68] transposed codes
        float* Enorm = stage + 64 * 68;      // [64]
        float* wsum  = stage + 64 * 68 + 64; // [4]
        const int cg = tid & 7;              // code subgroup: codes cg*8..cg*8+7
        const int rg = tid >> 3;             // 0..15
        const int r0 = rg * 4;               // 4 rows per thread
        float best[4]; int bidx[4];
#pragma unroll
        for (int i = 0; i < 4; ++i) { best[i] = 3.402823e38f; bidx[i] = 0; }

        for (int cc = 0; cc < 8; ++cc) {
#pragma unroll
            for (int t = 0; t < 8; ++t) {
                int idx = tid + t * THREADS;
                int dq = idx >> 6, c = idx & 63;
                float4 v = *((const float4*)(E + (size_t)(cc * 64 + c) * DVQ + dq * 4));
                EsT[(dq * 4 + 0) * 68 + c] = v.x;
                EsT[(dq * 4 + 1) * 68 + c] = v.y;
                EsT[(dq * 4 + 2) * 68 + c] = v.z;
                EsT[(dq * 4 + 3) * 68 + c] = v.w;
            }
            __syncthreads();
            if (tid < 64) {
                float s = 0.f;
#pragma unroll 8
                for (int d = 0; d < DVQ; ++d) { float e = EsT[d * 68 + tid]; s = fmaf(e, e, s); }
                Enorm[tid] = s;
            }
            __syncthreads();

            ull acc[4][4];
#pragma unroll
            for (int i = 0; i < 4; ++i)
#pragma unroll
                for (int j = 0; j < 4; ++j) acc[i][j] = 0ULL;

#pragma unroll
            for (int d4 = 0; d4 < 16; ++d4) {
                float4 a4[4];
#pragma unroll
                for (int i = 0; i < 4; ++i)
                    a4[i] = *((const float4*)(xqs + (r0 + i) * 68 + d4 * 4));
#pragma unroll
                for (int din = 0; din < 4; ++din) {
                    ull pa[4];
#pragma unroll
                    for (int i = 0; i < 4; ++i) {
                        float a = ((const float*)&a4[i])[din];
                        pa[i] = pk2(a, a);
                    }
                    const ulonglong2* bp =
                        (const ulonglong2*)(EsT + (d4 * 4 + din) * 68 + cg * 8);
                    ulonglong2 b01 = bp[0], b23 = bp[1];
                    ull b[4] = {b01.x, b01.y, b23.x, b23.y};
#pragma unroll
                    for (int i = 0; i < 4; ++i)
#pragma unroll
                        for (int j = 0; j < 4; ++j) ffma2(acc[i][j], pa[i], b[j]);
                }
            }
#pragma unroll
            for (int j = 0; j < 4; ++j) {
                int c0 = cg * 8 + 2 * j;
                float n0 = Enorm[c0], n1 = Enorm[c0 + 1];
                int g0 = cc * 64 + c0;
#pragma unroll
                for (int i = 0; i < 4; ++i) {
                    float2 dv = up2(acc[i][j]);
                    float s;
                    s = fmaf(-2.f, dv.x, n0); if (s < best[i]) { best[i] = s; bidx[i] = g0; }
                    s = fmaf(-2.f, dv.y, n1); if (s < best[i]) { best[i] = s; bidx[i] = g0 + 1; }
                }
            }
            __syncthreads();
        }
#pragma unroll
        for (int i = 0; i < 4; ++i) {
            float v = best[i]; int bi = bidx[i];
#pragma unroll
            for (int o = 1; o <= 4; o <<= 1) {
                float ov = __shfl_xor_sync(0xffffffffu, v, o);
                int   oi = __shfl_xor_sync(0xffffffffu, bi, o);
                if (ov < v || (ov == v && oi < bi)) { v = ov; bi = oi; }
            }
            best[i] = v; bidx[i] = bi;
        }
        float s_lat = 0.f;
        if (cg == 0) {
#pragma unroll
            for (int i = 0; i < 4; ++i) {
                int r = r0 + i;
                out_idx[row0 + r] = (float)bidx[i];
                const float* e = E + (size_t)bidx[i] * DVQ;
                float s = 0.f;
#pragma unroll 8
                for (int d = 0; d < DVQ; ++d) {
                    float diff = e[d] - xqs[r * 68 + d];
                    s = fmaf(diff, diff, s);
                }
                s_lat += s;
            }
        }
#pragma unroll
        for (int o = 16; o >= 1; o >>= 1)
            s_lat += __shfl_xor_sync(0xffffffffu, s_lat, o);
        if ((tid & 31) == 0) wsum[tid >> 5] = s_lat;
        __syncthreads();
        if (tid == 0) {
            float t = 0.f;
#pragma unroll
            for (int w = 0; w < 4; ++w) t += wsum[w];
            g_part[blockIdx.x] = t;
        }
        __syncthreads();   // stage reused by chain GEMMs below
    }

    // ============== MLP chain (activations resident in smem) =================
    // bufA = emb0
    gemm_chain(W_e1, b_e1, bufA, bufB, stage, tid, true);     // emb1 -> bufB
    gemm_chain(W_e2, b_e2, bufB, bufA, stage, tid, true);     // emb2 -> bufA
    gemm_merged(W_a0, b_a0, W_c0, b_c0, bufA, bufB, bufA,     // a_act -> bufB,
                stage, tid);                                  // c0 -> bufA
    gemm_chain(W_a1, b_a1, bufB, bufB, stage, tid, false);    // logits -> bufB
    gemm_chain(W_c1, b_c1, bufA, bufA, stage, tid, true);     // c1 -> bufA

    // ============== critic weight stage + softmax ============================
    stage[tid] = W_c2[tid];   // 128 threads = 128 weights

    {   // softmax over bufB rows -> out_probs
        int warp = tid >> 5, lane = tid & 31;
        for (int r = warp; r < RPC; r += 4) {
            float4 v = *((float4*)(bufB + r * 132 + lane * 4));
            float m = fmaxf(fmaxf(v.x, v.y), fmaxf(v.z, v.w));
#pragma unroll
            for (int o = 16; o >= 1; o >>= 1)
                m = fmaxf(m, __shfl_xor_sync(0xffffffffu, m, o));
            float e0 = expf(v.x - m), e1 = expf(v.y - m);
            float e2 = expf(v.z - m), e3 = expf(v.w - m);
            float s = (e0 + e1) + (e2 + e3);
#pragma unroll
            for (int o = 16; o >= 1; o >>= 1)
                s += __shfl_xor_sync(0xffffffffu, s, o);
            float4 p = make_float4(e0 / s, e1 / s, e2 / s, e3 / s);
            *((float4*)(out_probs + (size_t)(row0 + r) * 128 + lane * 4)) = p;
        }
    }
    __syncthreads();

    // ============== critic head: c1 @ W_c2 + b_c2 ============================
    if (tid < RPC) {
        float dotv = 0.f;
#pragma unroll 8
        for (int d = 0; d < 128; ++d)
            dotv = fmaf(bufA[tid * 132 + d], stage[d], dotv);
        out_critic[row0 + tid] = dotv + b_c2[0];
    }
    __syncthreads();

    // ============== last-CTA vq_loss finalize (single-launch design) =========
    __threadfence();
    unsigned int* flag = (unsigned int*)stage;
    if (tid == 0) {
        unsigned int p = atomicAdd(&g_ctr, 1u);
        flag[0] = (p == NCTA - 1) ? 1u : 0u;
    }
    __syncthreads();
    if (flag[0]) {
        float s = 0.f;
        for (int i = tid; i < NCTA; i += THREADS) s += g_part[i];
#pragma unroll
        for (int o = 16; o >= 1; o >>= 1)
            s += __shfl_xor_sync(0xffffffffu, s, o);
        if ((tid & 31) == 0) stage[8 + (tid >> 5)] = s;
        __syncthreads();
        if (tid == 0) {
            float t = 0.f;
#pragma unroll
            for (int w = 0; w < 4; ++w) t += stage[8 + w];
            out_vq[0] = (float)((double)t * (1.25 / ((double)NB * (double)DVQ)));
            g_ctr = 0;   // reset for next graph replay
        }
    }
}

// ---------------------------------------------------------------------------
extern "C" void kernel_launch(void* const* d_in, const int* in_sizes, int n_in,
                              void* d_out, int out_size)
{
    const float* x    = (const float*)d_in[0];
    const float* W_e0 = (const float*)d_in[1];
    const float* b_e0 = (const float*)d_in[2];
    const float* W_e1 = (const float*)d_in[3];
    const float* b_e1 = (const float*)d_in[4];
    const float* W_e2 = (const float*)d_in[5];
    const float* b_e2 = (const float*)d_in[6];
    const float* W_p  = (const float*)d_in[7];
    const float* b_p  = (const float*)d_in[8];
    const float* E    = (const float*)d_in[9];
    const float* W_a0 = (const float*)d_in[10];
    const float* b_a0 = (const float*)d_in[11];
    const float* W_a1 = (const float*)d_in[12];
    const float* b_a1 = (const float*)d_in[13];
    const float* W_c0 = (const float*)d_in[14];
    const float* b_c0 = (const float*)d_in[15];
    const float* W_c1 = (const float*)d_in[16];
    const float* b_c1 = (const float*)d_in[17];
    const float* W_c2 = (const float*)d_in[18];
    const float* b_c2 = (const float*)d_in[19];

    float* o = (float*)d_out;
    const size_t P = (size_t)NB * 128;
    float* out_probs  = o;
    float* out_critic = o + P;
    float* out_vq     = o + P + NB;
    float* out_idx    = o + P + NB + 1;

    static bool inited = false;
    if (!inited) {
        cudaFuncSetAttribute(acsq_kernel,
                             cudaFuncAttributeMaxDynamicSharedMemorySize,
                             SMEM_BYTES);
        inited = true;
    }

    // ONE launch per call -> every ncu -s index lands on the main kernel.
    acsq_kernel<<<NCTA, THREADS, SMEM_BYTES>>>(
        x, W_e0, b_e0, W_e1, b_e1, W_e2, b_e2, W_p, b_p, E,
        W_a0, b_a0, W_a1, b_a1, W_c0, b_c0, W_c1, b_c1, W_c2, b_c2,
        out_probs, out_critic, out_vq, out_idx);
}